// round 15
// baseline (speedup 1.0000x reference)
#include <cuda_runtime.h>
#include <cuda_fp16.h>
#include <math_constants.h>
#include <cstdint>

#define B_SAMPLES 32768
#define D_DIM 256
#define C_CLASSES 2048
#define NTILES 16              // C / 128
#define EPSV 1e-12f

// ---------------- scratch (device globals; no allocation) ----------------
// Invariant: every buffer that must start zeroed is returned to zero by the
// end of each kernel_launch call (globals are zero-initialized at load).
__device__ __half g_A[B_SAMPLES * D_DIM];          // normalized feats, f16 (16 MB)
__device__ __half g_B[C_CLASSES * D_DIM];          // centroids, f16 (1 MB)
__device__ float g_sums[C_CLASSES * D_DIM];        // fp32 class sums; re-zeroed in k_centroids
__device__ float g_counts[C_CLASSES];              // re-zeroed in k_centroids
__device__ float g_cnt2[C_CLASSES];                // stable copy for k_loss
__device__ float g_pen[C_CLASSES];                 // cn2 if count>0 else +inf
__device__ float g_sval[B_SAMPLES * NTILES];       // per-sample per-tile best score
__device__ float g_own[B_SAMPLES];                 // f_i . centroid[label_i] (f16-accum)
__device__ float g_acc[2];                         // {loss_sum, valid_cnt}; reset in k_loss
__device__ unsigned int g_done;                    // reset in k_loss

// ---------------- helpers ----------------
__device__ __forceinline__ uint32_t smem_u32(const void* p) {
    uint32_t a;
    asm("{ .reg .u64 t; cvta.to.shared.u64 t, %1; cvt.u32.u64 %0, t; }" : "=r"(a) : "l"(p));
    return a;
}
__device__ __forceinline__ void cp16(uint32_t dst, const void* src) {
    asm volatile("cp.async.cg.shared.global [%0], [%1], 16;" :: "r"(dst), "l"(src) : "memory");
}
template <int N>
__device__ __forceinline__ void cp_wait() {
    asm volatile("cp.async.wait_group %0;" :: "n"(N) : "memory");
}
__device__ __forceinline__ void cp_commit() {
    asm volatile("cp.async.commit_group;" ::: "memory");
}
__device__ __forceinline__ void ldsm_x4(uint32_t& r0, uint32_t& r1, uint32_t& r2, uint32_t& r3,
                                        uint32_t addr) {
    asm volatile("ldmatrix.sync.aligned.m8n8.x4.shared.b16 {%0,%1,%2,%3}, [%4];"
                 : "=r"(r0), "=r"(r1), "=r"(r2), "=r"(r3) : "r"(addr));
}
// f16 MMA with f16 accumulators: D/C are 2 regs (4 halves)
__device__ __forceinline__ void mma_f16acc(uint32_t* d, const uint32_t* a,
                                           uint32_t b0, uint32_t b1) {
    asm volatile(
        "mma.sync.aligned.m16n8k16.row.col.f16.f16.f16.f16 "
        "{%0,%1}, {%2,%3,%4,%5}, {%6,%7}, {%0,%1};"
        : "+r"(d[0]), "+r"(d[1])
        : "r"(a[0]), "r"(a[1]), "r"(a[2]), "r"(a[3]), "r"(b0), "r"(b1));
}
__device__ __forceinline__ uint32_t pack_f16(float x, float y) {
    __half2 h = __floats2half2_rn(x, y);
    return *(uint32_t*)&h;
}
// vector fp32 atomic add (sm_90+: red.global.v4.f32)
__device__ __forceinline__ void red_add_f4(float* addr, float4 v) {
    asm volatile("red.global.add.v4.f32 [%0], {%1, %2, %3, %4};"
                 :: "l"(addr), "f"(v.x), "f"(v.y), "f"(v.z), "f"(v.w) : "memory");
}

// ---------------- K1: normalize + f16 store + segment sums ----------------
__global__ void k_normalize(const float* __restrict__ feats,
                            const int* __restrict__ labels) {
    int warp = (blockIdx.x * blockDim.x + threadIdx.x) >> 5;
    int lane = threadIdx.x & 31;
    if (warp >= B_SAMPLES) return;

    const float4* frow = (const float4*)(feats + (size_t)warp * D_DIM);
    float4 v0 = frow[lane];
    float4 v1 = frow[lane + 32];

    float ss = v0.x*v0.x + v0.y*v0.y + v0.z*v0.z + v0.w*v0.w
             + v1.x*v1.x + v1.y*v1.y + v1.z*v1.z + v1.w*v1.w;
    #pragma unroll
    for (int off = 16; off >= 1; off >>= 1) ss += __shfl_xor_sync(0xffffffffu, ss, off);

    float inv = 1.0f / fmaxf(sqrtf(ss), EPSV);
    v0.x *= inv; v0.y *= inv; v0.z *= inv; v0.w *= inv;
    v1.x *= inv; v1.y *= inv; v1.z *= inv; v1.w *= inv;

    int d0 = lane * 4;
    __half* ar = g_A + (size_t)warp * D_DIM;
    *(uint2*)(ar + d0) = make_uint2(pack_f16(v0.x, v0.y), pack_f16(v0.z, v0.w));
    *(uint2*)(ar + 128 + d0) = make_uint2(pack_f16(v1.x, v1.y), pack_f16(v1.z, v1.w));

    int lab = labels[warp];
    float* srow = g_sums + (size_t)lab * D_DIM;
    red_add_f4(&srow[d0], v0);
    red_add_f4(&srow[128 + d0], v1);
    if (lane == 0) atomicAdd(&g_counts[lab], 1.0f);
}

// ---------------- K2: centroids -> f16 + penalty; re-zero sums/counts ----------------
__global__ void k_centroids() {
    int warp = (blockIdx.x * blockDim.x + threadIdx.x) >> 5;
    int lane = threadIdx.x & 31;
    if (warp >= C_CLASSES) return;

    float cnt = g_counts[warp];
    float inv = 1.0f / fmaxf(cnt, 1.0f);

    float4* srow = (float4*)(g_sums + (size_t)warp * D_DIM);
    float4 s0 = srow[lane];
    float4 s1 = srow[lane + 32];
    float4 c0 = make_float4(s0.x*inv, s0.y*inv, s0.z*inv, s0.w*inv);
    float4 c1 = make_float4(s1.x*inv, s1.y*inv, s1.z*inv, s1.w*inv);

    // restore zeros for the next kernel_launch call
    float4 z = make_float4(0.0f, 0.0f, 0.0f, 0.0f);
    srow[lane] = z;
    srow[lane + 32] = z;

    int d0 = lane * 4;
    __half* br = g_B + (size_t)warp * D_DIM;
    *(uint2*)(br + d0) = make_uint2(pack_f16(c0.x, c0.y), pack_f16(c0.z, c0.w));
    *(uint2*)(br + 128 + d0) = make_uint2(pack_f16(c1.x, c1.y), pack_f16(c1.z, c1.w));

    float ss = c0.x*c0.x + c0.y*c0.y + c0.z*c0.z + c0.w*c0.w
             + c1.x*c1.x + c1.y*c1.y + c1.z*c1.z + c1.w*c1.w;
    #pragma unroll
    for (int off = 16; off >= 1; off >>= 1) ss += __shfl_xor_sync(0xffffffffu, ss, off);

    if (lane == 0) {
        g_pen[warp] = (cnt > 0.0f) ? ss : CUDART_INF_F;
        g_cnt2[warp] = cnt;
        g_counts[warp] = 0.0f;   // ready for next call
    }
}

// ---------------- K3: f16-accum mma GEMM + masked max + own-dot export ----------------
#define SSTRIDE 40                      // f16 elems per smem row (80 B)
#define TILE_BYTES (128 * SSTRIDE * 2)  // 10240 B
#define STAGE_BYTES (2 * TILE_BYTES)    // 20480 B
#define NSTAGES 3
#define DSMEM_TOTAL (NSTAGES * STAGE_BYTES)  // 61440 B

__global__ __launch_bounds__(256, 3)
void k_gemm_f16(const int* __restrict__ labels) {
    extern __shared__ __align__(16) char dsm[];
    __shared__ float s_pen[128];
    __shared__ int   s_lab[128];
    __shared__ float s_val[128];

    int tid = threadIdx.x;
    int wid = tid >> 5;
    int lane = tid & 31;
    int arow0 = blockIdx.x * 128;
    int brow0 = blockIdx.y * 128;

    if (tid < 128) {
        s_pen[tid] = g_pen[brow0 + tid];
        s_lab[tid] = labels[arow0 + tid];
    }

    uint32_t sb = smem_u32(dsm);

    const __half* gA0 = g_A + (size_t)(arow0 + (tid >> 2)) * D_DIM + (tid & 3) * 8;
    const __half* gA1 = gA0 + (size_t)64 * D_DIM;
    const __half* gB0 = g_B + (size_t)(brow0 + (tid >> 2)) * D_DIM + (tid & 3) * 8;
    const __half* gB1 = gB0 + (size_t)64 * D_DIM;
    uint32_t so0 = (uint32_t)((tid >> 2) * SSTRIDE * 2 + (tid & 3) * 16);
    uint32_t so1 = so0 + 64 * SSTRIDE * 2;

    auto stage = [&](int kb, int s) {
        uint32_t a_b = sb + s * STAGE_BYTES;
        uint32_t b_b = a_b + TILE_BYTES;
        cp16(a_b + so0, gA0 + kb * 32);
        cp16(a_b + so1, gA1 + kb * 32);
        cp16(b_b + so0, gB0 + kb * 32);
        cp16(b_b + so1, gB1 + kb * 32);
        cp_commit();
    };

    uint32_t acc[2][8][2];
    #pragma unroll
    for (int mt = 0; mt < 2; mt++)
        #pragma unroll
        for (int n8 = 0; n8 < 8; n8++) { acc[mt][n8][0] = 0u; acc[mt][n8][1] = 0u; }

    int lr = lane & 15;
    int koff = (lane >> 4) * 8;
    uint32_t aoff = (uint32_t)(((wid & 3) * 32 + lr) * SSTRIDE + koff) * 2;
    uint32_t boff = (uint32_t)(((wid >> 2) * 64 + lr) * SSTRIDE + koff) * 2;

    stage(0, 0);
    stage(1, 1);

    #pragma unroll
    for (int kb = 0; kb < 8; kb++) {
        const int s = kb % 3;
        if (kb < 7) cp_wait<1>();
        else        cp_wait<0>();
        __syncthreads();
        if (kb + 2 < 8) stage(kb + 2, (kb + 2) % 3);

        uint32_t a_b = sb + s * STAGE_BYTES;
        uint32_t b_b = a_b + TILE_BYTES;
        #pragma unroll
        for (int ks = 0; ks < 2; ks++) {
            uint32_t a[2][4], b[4][4];
            #pragma unroll
            for (int mt = 0; mt < 2; mt++)
                ldsm_x4(a[mt][0], a[mt][1], a[mt][2], a[mt][3],
                        a_b + aoff + (uint32_t)(mt * 16 * SSTRIDE * 2 + ks * 32));
            #pragma unroll
            for (int nt = 0; nt < 4; nt++)
                ldsm_x4(b[nt][0], b[nt][1], b[nt][2], b[nt][3],
                        b_b + boff + (uint32_t)(nt * 16 * SSTRIDE * 2 + ks * 32));
            #pragma unroll
            for (int mt = 0; mt < 2; mt++)
                #pragma unroll
                for (int n8 = 0; n8 < 8; n8++) {
                    int nt = n8 >> 1, o = n8 & 1;
                    mma_f16acc(acc[mt][n8], a[mt], b[nt][o], b[nt][o + 2]);
                }
        }
    }

    // epilogue: per-row masked max over this CTA's 128 classes + own-dot export
    int r4 = lane >> 2;
    int c2 = lane & 3;
    float rmax[4];
    #pragma unroll
    for (int mt = 0; mt < 2; mt++) {
        #pragma unroll
        for (int h = 0; h < 2; h++) {
            int m_local = (wid & 3) * 32 + mt * 16 + h * 8 + r4;
            int lab = s_lab[m_local];
            float mx = -CUDART_INF_F;
            #pragma unroll
            for (int n8 = 0; n8 < 8; n8++) {
                int n_local = (wid >> 2) * 64 + n8 * 8 + c2 * 2;
                int cls0 = brow0 + n_local;
                float2 dv = __half22float2(*(const __half2*)&acc[mt][n8][h]);
                float sc0 = 2.0f * dv.x - s_pen[n_local];
                float sc1 = 2.0f * dv.y - s_pen[n_local + 1];
                if (cls0 != lab)     mx = fmaxf(mx, sc0);
                else                 g_own[arow0 + m_local] = dv.x;
                if (cls0 + 1 != lab) mx = fmaxf(mx, sc1);
                else                 g_own[arow0 + m_local] = dv.y;
            }
            rmax[mt * 2 + h] = mx;
        }
    }
    #pragma unroll
    for (int off = 1; off <= 2; off <<= 1)
        #pragma unroll
        for (int i = 0; i < 4; i++)
            rmax[i] = fmaxf(rmax[i], __shfl_xor_sync(0xffffffffu, rmax[i], off));

    if (wid < 4 && c2 == 0) {
        #pragma unroll
        for (int i = 0; i < 4; i++) {
            int m_local = (wid & 3) * 32 + (i >> 1) * 16 + (i & 1) * 8 + r4;
            s_val[m_local] = rmax[i];
        }
    }
    __syncthreads();
    if (wid >= 4 && c2 == 0) {
        #pragma unroll
        for (int i = 0; i < 4; i++) {
            int m_local = (wid & 3) * 32 + (i >> 1) * 16 + (i & 1) * 8 + r4;
            g_sval[(size_t)(arow0 + m_local) * NTILES + blockIdx.y] =
                fmaxf(rmax[i], s_val[m_local]);
        }
    }
}

// ---------------- K4: scalar loss from GEMM scores + finalize ----------------
__device__ __forceinline__ float softplus_stable(float x) {
    return (x > 0.0f) ? (x + log1pf(expf(-x))) : log1pf(expf(x));
}
#define LOSS_BLOCK 64
#define LOSS_BLOCKS (B_SAMPLES / LOSS_BLOCK)   // 512 CTAs -> >3 per SM

__global__ __launch_bounds__(LOSS_BLOCK)
void k_loss(const int* __restrict__ labels,
            const int* __restrict__ epoch_p,
            float* __restrict__ out) {
    int i = blockIdx.x * LOSS_BLOCK + threadIdx.x;
    int lab = labels[i];
    float cnt = g_cnt2[lab];

    // max over the 16 per-tile candidates (contiguous 64 B per sample)
    const float4* sv = (const float4*)(g_sval + (size_t)i * NTILES);
    float smax = -CUDART_INF_F;
    #pragma unroll
    for (int j = 0; j < 4; j++) {
        float4 q = sv[j];
        smax = fmaxf(smax, fmaxf(fmaxf(q.x, q.y), fmaxf(q.z, q.w)));
    }

    float lv = 0.0f, cv = 0.0f;
    if (cnt > 1.0f && smax > -1e37f) {
        float own = g_own[i];
        float cn2 = g_pen[lab];
        float m = cnt - 1.0f;
        float invm = 1.0f / m;
        float fS = cnt * own;
        float S2 = cnt * cnt * cn2;
        float dp2 = 1.0f - 2.0f * (fS - 1.0f) * invm
                  + (S2 - 2.0f * fS + 1.0f) * invm * invm;
        float dp = sqrtf(fmaxf(dp2, 0.0f) + EPSV);
        float dn = sqrtf(fmaxf(1.0f - smax, EPSV));
        int iv = epoch_p[0];
        float ev = (iv >= 0 && iv < 100000) ? (float)iv : __int_as_float(iv);
        float temp = fminf(0.3f + 0.02f * ev, 1.0f);
        lv = softplus_stable((dp - dn) / temp);
        cv = 1.0f;
    }
    #pragma unroll
    for (int off = 16; off >= 1; off >>= 1) {
        lv += __shfl_xor_sync(0xffffffffu, lv, off);
        cv += __shfl_xor_sync(0xffffffffu, cv, off);
    }
    if ((threadIdx.x & 31) == 0) {
        atomicAdd(&g_acc[0], lv);
        atomicAdd(&g_acc[1], cv);
    }
    __syncthreads();
    if (threadIdx.x == 0) {
        __threadfence();
        unsigned int done = atomicAdd(&g_done, 1u);
        if (done == LOSS_BLOCKS - 1) {
            float sum = g_acc[0];
            float c = g_acc[1];
            out[0] = (c > 0.0f) ? (sum / fmaxf(c, 1.0f)) : 0.0f;
            // restore scratch for the next kernel_launch call
            g_acc[0] = 0.0f;
            g_acc[1] = 0.0f;
            g_done = 0u;
        }
    }
}

// ---------------- launch ----------------
extern "C" void kernel_launch(void* const* d_in, const int* in_sizes, int n_in,
                              void* d_out, int out_size) {
    const float* feats = (const float*)d_in[0];
    const int* labels = (const int*)d_in[1];
    const int* epoch = (const int*)d_in[2];
    float* out = (float*)d_out;

    static int configured = 0;
    if (!configured) {
        cudaFuncSetAttribute(k_gemm_f16, cudaFuncAttributeMaxDynamicSharedMemorySize,
                             DSMEM_TOTAL);
        configured = 1;
    }

    k_normalize<<<(B_SAMPLES * 32) / 256, 256>>>(feats, labels);
    k_centroids<<<(C_CLASSES * 32) / 256, 256>>>();
    k_gemm_f16<<<dim3(B_SAMPLES / 128, C_CLASSES / 128), 256, DSMEM_TOTAL>>>(labels);
    k_loss<<<LOSS_BLOCKS, LOSS_BLOCK>>>(labels, epoch, out);
}

// round 16
// speedup vs baseline: 1.0378x; 1.0378x over previous
#include <cuda_runtime.h>
#include <cuda_fp16.h>
#include <math_constants.h>
#include <cstdint>

#define B_SAMPLES 32768
#define D_DIM 256
#define C_CLASSES 2048
#define EPSV 1e-12f

// ---------------- scratch (device globals; no allocation) ----------------
// Invariant: every buffer that must start zeroed is returned to zero by the
// end of each kernel_launch call (globals are zero-initialized at load).
__device__ __half g_A[B_SAMPLES * D_DIM];          // normalized feats, f16 (16 MB)
__device__ __half g_B[C_CLASSES * D_DIM];          // centroids, f16 (1 MB)
__device__ float g_sums[C_CLASSES * D_DIM];        // fp32 class sums; re-zeroed in k_centroids
__device__ float g_counts[C_CLASSES];              // re-zeroed in k_centroids
__device__ float g_cnt2[C_CLASSES];                // stable copy for k_loss
__device__ float g_pen[C_CLASSES];                 // cn2 if count>0 else +inf
__device__ unsigned int g_smax_enc[B_SAMPLES];     // ordered-encoded max score; re-zeroed in k_loss
__device__ float g_own[B_SAMPLES];                 // f_i . centroid[label_i] (f16-accum)
__device__ float g_acc[2];                         // {loss_sum, valid_cnt}; reset in k_loss
__device__ unsigned int g_done;                    // reset in k_loss

// ---------------- helpers ----------------
__device__ __forceinline__ uint32_t smem_u32(const void* p) {
    uint32_t a;
    asm("{ .reg .u64 t; cvta.to.shared.u64 t, %1; cvt.u32.u64 %0, t; }" : "=r"(a) : "l"(p));
    return a;
}
__device__ __forceinline__ void cp16(uint32_t dst, const void* src) {
    asm volatile("cp.async.cg.shared.global [%0], [%1], 16;" :: "r"(dst), "l"(src) : "memory");
}
template <int N>
__device__ __forceinline__ void cp_wait() {
    asm volatile("cp.async.wait_group %0;" :: "n"(N) : "memory");
}
__device__ __forceinline__ void cp_commit() {
    asm volatile("cp.async.commit_group;" ::: "memory");
}
__device__ __forceinline__ void ldsm_x4(uint32_t& r0, uint32_t& r1, uint32_t& r2, uint32_t& r3,
                                        uint32_t addr) {
    asm volatile("ldmatrix.sync.aligned.m8n8.x4.shared.b16 {%0,%1,%2,%3}, [%4];"
                 : "=r"(r0), "=r"(r1), "=r"(r2), "=r"(r3) : "r"(addr));
}
// f16 MMA with f16 accumulators: D/C are 2 regs (4 halves)
__device__ __forceinline__ void mma_f16acc(uint32_t* d, const uint32_t* a,
                                           uint32_t b0, uint32_t b1) {
    asm volatile(
        "mma.sync.aligned.m16n8k16.row.col.f16.f16.f16.f16 "
        "{%0,%1}, {%2,%3,%4,%5}, {%6,%7}, {%0,%1};"
        : "+r"(d[0]), "+r"(d[1])
        : "r"(a[0]), "r"(a[1]), "r"(a[2]), "r"(a[3]), "r"(b0), "r"(b1));
}
__device__ __forceinline__ uint32_t pack_f16(float x, float y) {
    __half2 h = __floats2half2_rn(x, y);
    return *(uint32_t*)&h;
}
// vector fp32 atomic add (sm_90+: red.global.v4.f32)
__device__ __forceinline__ void red_add_f4(float* addr, float4 v) {
    asm volatile("red.global.add.v4.f32 [%0], {%1, %2, %3, %4};"
                 :: "l"(addr), "f"(v.x), "f"(v.y), "f"(v.z), "f"(v.w) : "memory");
}
// monotone float<->u32 encoding for atomicMax
__device__ __forceinline__ uint32_t enc_f32(float f) {
    uint32_t b = __float_as_uint(f);
    return b ^ ((b & 0x80000000u) ? 0xFFFFFFFFu : 0x80000000u);
}
__device__ __forceinline__ float dec_f32(uint32_t u) {
    uint32_t b = u ^ ((u & 0x80000000u) ? 0x80000000u : 0xFFFFFFFFu);
    return __uint_as_float(b);
}

// ---------------- K1: normalize + f16 store + segment sums ----------------
__global__ void k_normalize(const float* __restrict__ feats,
                            const int* __restrict__ labels) {
    int warp = (blockIdx.x * blockDim.x + threadIdx.x) >> 5;
    int lane = threadIdx.x & 31;
    if (warp >= B_SAMPLES) return;

    const float4* frow = (const float4*)(feats + (size_t)warp * D_DIM);
    float4 v0 = frow[lane];
    float4 v1 = frow[lane + 32];

    float ss = v0.x*v0.x + v0.y*v0.y + v0.z*v0.z + v0.w*v0.w
             + v1.x*v1.x + v1.y*v1.y + v1.z*v1.z + v1.w*v1.w;
    #pragma unroll
    for (int off = 16; off >= 1; off >>= 1) ss += __shfl_xor_sync(0xffffffffu, ss, off);

    float inv = 1.0f / fmaxf(sqrtf(ss), EPSV);
    v0.x *= inv; v0.y *= inv; v0.z *= inv; v0.w *= inv;
    v1.x *= inv; v1.y *= inv; v1.z *= inv; v1.w *= inv;

    int d0 = lane * 4;
    __half* ar = g_A + (size_t)warp * D_DIM;
    *(uint2*)(ar + d0) = make_uint2(pack_f16(v0.x, v0.y), pack_f16(v0.z, v0.w));
    *(uint2*)(ar + 128 + d0) = make_uint2(pack_f16(v1.x, v1.y), pack_f16(v1.z, v1.w));

    int lab = labels[warp];
    float* srow = g_sums + (size_t)lab * D_DIM;
    red_add_f4(&srow[d0], v0);
    red_add_f4(&srow[128 + d0], v1);
    if (lane == 0) atomicAdd(&g_counts[lab], 1.0f);
}

// ---------------- K2: centroids -> f16 + penalty; re-zero sums/counts ----------------
__global__ void k_centroids() {
    int warp = (blockIdx.x * blockDim.x + threadIdx.x) >> 5;
    int lane = threadIdx.x & 31;
    if (warp >= C_CLASSES) return;

    float cnt = g_counts[warp];
    float inv = 1.0f / fmaxf(cnt, 1.0f);

    float4* srow = (float4*)(g_sums + (size_t)warp * D_DIM);
    float4 s0 = srow[lane];
    float4 s1 = srow[lane + 32];
    float4 c0 = make_float4(s0.x*inv, s0.y*inv, s0.z*inv, s0.w*inv);
    float4 c1 = make_float4(s1.x*inv, s1.y*inv, s1.z*inv, s1.w*inv);

    // restore zeros for the next kernel_launch call
    float4 z = make_float4(0.0f, 0.0f, 0.0f, 0.0f);
    srow[lane] = z;
    srow[lane + 32] = z;

    int d0 = lane * 4;
    __half* br = g_B + (size_t)warp * D_DIM;
    *(uint2*)(br + d0) = make_uint2(pack_f16(c0.x, c0.y), pack_f16(c0.z, c0.w));
    *(uint2*)(br + 128 + d0) = make_uint2(pack_f16(c1.x, c1.y), pack_f16(c1.z, c1.w));

    float ss = c0.x*c0.x + c0.y*c0.y + c0.z*c0.z + c0.w*c0.w
             + c1.x*c1.x + c1.y*c1.y + c1.z*c1.z + c1.w*c1.w;
    #pragma unroll
    for (int off = 16; off >= 1; off >>= 1) ss += __shfl_xor_sync(0xffffffffu, ss, off);

    if (lane == 0) {
        g_pen[warp] = (cnt > 0.0f) ? ss : CUDART_INF_F;
        g_cnt2[warp] = cnt;
        g_counts[warp] = 0.0f;   // ready for next call
    }
}

// ---------------- K3: f16-accum mma GEMM + atomic masked max + own-dot export ----------------
#define SSTRIDE 40                      // f16 elems per smem row (80 B)
#define TILE_BYTES (128 * SSTRIDE * 2)  // 10240 B
#define STAGE_BYTES (2 * TILE_BYTES)    // 20480 B
#define NSTAGES 3
#define DSMEM_TOTAL (NSTAGES * STAGE_BYTES)  // 61440 B

__global__ __launch_bounds__(256, 3)
void k_gemm_f16(const int* __restrict__ labels) {
    extern __shared__ __align__(16) char dsm[];
    __shared__ float s_pen[128];
    __shared__ int   s_lab[128];

    int tid = threadIdx.x;
    int wid = tid >> 5;
    int lane = tid & 31;
    int arow0 = blockIdx.x * 128;
    int brow0 = blockIdx.y * 128;

    if (tid < 128) {
        s_pen[tid] = g_pen[brow0 + tid];
        s_lab[tid] = labels[arow0 + tid];
    }

    uint32_t sb = smem_u32(dsm);

    const __half* gA0 = g_A + (size_t)(arow0 + (tid >> 2)) * D_DIM + (tid & 3) * 8;
    const __half* gA1 = gA0 + (size_t)64 * D_DIM;
    const __half* gB0 = g_B + (size_t)(brow0 + (tid >> 2)) * D_DIM + (tid & 3) * 8;
    const __half* gB1 = gB0 + (size_t)64 * D_DIM;
    uint32_t so0 = (uint32_t)((tid >> 2) * SSTRIDE * 2 + (tid & 3) * 16);
    uint32_t so1 = so0 + 64 * SSTRIDE * 2;

    auto stage = [&](int kb, int s) {
        uint32_t a_b = sb + s * STAGE_BYTES;
        uint32_t b_b = a_b + TILE_BYTES;
        cp16(a_b + so0, gA0 + kb * 32);
        cp16(a_b + so1, gA1 + kb * 32);
        cp16(b_b + so0, gB0 + kb * 32);
        cp16(b_b + so1, gB1 + kb * 32);
        cp_commit();
    };

    uint32_t acc[2][8][2];
    #pragma unroll
    for (int mt = 0; mt < 2; mt++)
        #pragma unroll
        for (int n8 = 0; n8 < 8; n8++) { acc[mt][n8][0] = 0u; acc[mt][n8][1] = 0u; }

    int lr = lane & 15;
    int koff = (lane >> 4) * 8;
    uint32_t aoff = (uint32_t)(((wid & 3) * 32 + lr) * SSTRIDE + koff) * 2;
    uint32_t boff = (uint32_t)(((wid >> 2) * 64 + lr) * SSTRIDE + koff) * 2;

    stage(0, 0);
    stage(1, 1);

    #pragma unroll
    for (int kb = 0; kb < 8; kb++) {
        const int s = kb % 3;
        if (kb < 7) cp_wait<1>();
        else        cp_wait<0>();
        __syncthreads();
        if (kb + 2 < 8) stage(kb + 2, (kb + 2) % 3);

        uint32_t a_b = sb + s * STAGE_BYTES;
        uint32_t b_b = a_b + TILE_BYTES;
        #pragma unroll
        for (int ks = 0; ks < 2; ks++) {
            uint32_t a[2][4], b[4][4];
            #pragma unroll
            for (int mt = 0; mt < 2; mt++)
                ldsm_x4(a[mt][0], a[mt][1], a[mt][2], a[mt][3],
                        a_b + aoff + (uint32_t)(mt * 16 * SSTRIDE * 2 + ks * 32));
            #pragma unroll
            for (int nt = 0; nt < 4; nt++)
                ldsm_x4(b[nt][0], b[nt][1], b[nt][2], b[nt][3],
                        b_b + boff + (uint32_t)(nt * 16 * SSTRIDE * 2 + ks * 32));
            #pragma unroll
            for (int mt = 0; mt < 2; mt++)
                #pragma unroll
                for (int n8 = 0; n8 < 8; n8++) {
                    int nt = n8 >> 1, o = n8 & 1;
                    mma_f16acc(acc[mt][n8], a[mt], b[nt][o], b[nt][o + 2]);
                }
        }
    }

    // epilogue: per-row masked max over this CTA's 128 classes + own-dot export.
    // Cross-warp / cross-CTA merge via ordered-encoded atomicMax (no smem pass).
    int r4 = lane >> 2;
    int c2 = lane & 3;
    float rmax[4];
    #pragma unroll
    for (int mt = 0; mt < 2; mt++) {
        #pragma unroll
        for (int h = 0; h < 2; h++) {
            int m_local = (wid & 3) * 32 + mt * 16 + h * 8 + r4;
            int lab = s_lab[m_local];
            float mx = -CUDART_INF_F;
            #pragma unroll
            for (int n8 = 0; n8 < 8; n8++) {
                int n_local = (wid >> 2) * 64 + n8 * 8 + c2 * 2;
                int cls0 = brow0 + n_local;
                float2 dv = __half22float2(*(const __half2*)&acc[mt][n8][h]);
                float sc0 = 2.0f * dv.x - s_pen[n_local];
                float sc1 = 2.0f * dv.y - s_pen[n_local + 1];
                if (cls0 != lab)     mx = fmaxf(mx, sc0);
                else                 g_own[arow0 + m_local] = dv.x;
                if (cls0 + 1 != lab) mx = fmaxf(mx, sc1);
                else                 g_own[arow0 + m_local] = dv.y;
            }
            rmax[mt * 2 + h] = mx;
        }
    }
    #pragma unroll
    for (int off = 1; off <= 2; off <<= 1)
        #pragma unroll
        for (int i = 0; i < 4; i++)
            rmax[i] = fmaxf(rmax[i], __shfl_xor_sync(0xffffffffu, rmax[i], off));

    if (c2 == 0) {
        #pragma unroll
        for (int i = 0; i < 4; i++) {
            int m_local = (wid & 3) * 32 + (i >> 1) * 16 + (i & 1) * 8 + r4;
            atomicMax(&g_smax_enc[arow0 + m_local], enc_f32(rmax[i]));
        }
    }
}

// ---------------- K4: scalar loss from GEMM scores + finalize ----------------
__device__ __forceinline__ float softplus_stable(float x) {
    return (x > 0.0f) ? (x + log1pf(expf(-x))) : log1pf(expf(x));
}
#define LOSS_BLOCKS (B_SAMPLES / 256)

__global__ __launch_bounds__(256)
void k_loss(const int* __restrict__ labels,
            const int* __restrict__ epoch_p,
            float* __restrict__ out) {
    __shared__ float s_part[2];
    if (threadIdx.x == 0) { s_part[0] = 0.0f; s_part[1] = 0.0f; }
    __syncthreads();

    int i = blockIdx.x * 256 + threadIdx.x;
    int lab = labels[i];
    float cnt = g_cnt2[lab];

    float smax = dec_f32(g_smax_enc[i]);
    g_smax_enc[i] = 0u;   // restore for next kernel_launch call

    float lv = 0.0f, cv = 0.0f;
    if (cnt > 1.0f && smax > -1e37f) {
        float own = g_own[i];
        float cn2 = g_pen[lab];
        float m = cnt - 1.0f;
        float invm = 1.0f / m;
        float fS = cnt * own;
        float S2 = cnt * cnt * cn2;
        float dp2 = 1.0f - 2.0f * (fS - 1.0f) * invm
                  + (S2 - 2.0f * fS + 1.0f) * invm * invm;
        float dp = sqrtf(fmaxf(dp2, 0.0f) + EPSV);
        float dn = sqrtf(fmaxf(1.0f - smax, EPSV));
        int iv = epoch_p[0];
        float ev = (iv >= 0 && iv < 100000) ? (float)iv : __int_as_float(iv);
        float temp = fminf(0.3f + 0.02f * ev, 1.0f);
        lv = softplus_stable((dp - dn) / temp);
        cv = 1.0f;
    }
    #pragma unroll
    for (int off = 16; off >= 1; off >>= 1) {
        lv += __shfl_xor_sync(0xffffffffu, lv, off);
        cv += __shfl_xor_sync(0xffffffffu, cv, off);
    }
    if ((threadIdx.x & 31) == 0) {
        atomicAdd(&s_part[0], lv);
        atomicAdd(&s_part[1], cv);
    }
    __syncthreads();
    if (threadIdx.x == 0) {
        atomicAdd(&g_acc[0], s_part[0]);
        atomicAdd(&g_acc[1], s_part[1]);
        __threadfence();
        unsigned int done = atomicAdd(&g_done, 1u);
        if (done == LOSS_BLOCKS - 1) {
            float sum = g_acc[0];
            float c = g_acc[1];
            out[0] = (c > 0.0f) ? (sum / fmaxf(c, 1.0f)) : 0.0f;
            // restore scratch for the next kernel_launch call
            g_acc[0] = 0.0f;
            g_acc[1] = 0.0f;
            g_done = 0u;
        }
    }
}

// ---------------- launch ----------------
extern "C" void kernel_launch(void* const* d_in, const int* in_sizes, int n_in,
                              void* d_out, int out_size) {
    const float* feats = (const float*)d_in[0];
    const int* labels = (const int*)d_in[1];
    const int* epoch = (const int*)d_in[2];
    float* out = (float*)d_out;

    static int configured = 0;
    if (!configured) {
        cudaFuncSetAttribute(k_gemm_f16, cudaFuncAttributeMaxDynamicSharedMemorySize,
                             DSMEM_TOTAL);
        configured = 1;
    }

    k_normalize<<<(B_SAMPLES * 32) / 256, 256>>>(feats, labels);
    k_centroids<<<(C_CLASSES * 32) / 256, 256>>>();
    k_gemm_f16<<<dim3(B_SAMPLES / 128, C_CLASSES / 128), 256, DSMEM_TOTAL>>>(labels);
    k_loss<<<LOSS_BLOCKS, 256>>>(labels, epoch, out);
}